// round 3
// baseline (speedup 1.0000x reference)
#include <cuda_runtime.h>
#include <math.h>

// ---------------- problem constants ----------------
#define NN   32
#define PP   992
#define DD   256
#define MM   14
#define OC   151
#define RC   51
#define RED  64
#define KIN  4251          // 4096 + 151 + 4
#define KC   1063          // obj-emb K chunk (4 chunks)
#define SP2  196           // 14*14

// ---------------- device scratch ----------------
__device__ float g_part[4 * NN * DD];        // obj-emb split-K partials
__device__ float g_feats[(NN + PP) * DD];    // [obj_feats ; rel_feats]
__device__ float g_sall[PP * 3 * DD];        // masked means -> gated (in place)
__device__ float g_h1[PP * DD];              // rel MLP hidden
__device__ float g_h[(NN + PP) * DD];        // feats @ W_gcn

// ============================================================
// A1: obj-emb GEMM1 split-K partials. grid = 128 (= 4 chunks x 32 rows)
// ============================================================
__global__ __launch_bounds__(256)
void obj_emb1_kernel(const float* __restrict__ roi,
                     const float* __restrict__ logits,
                     const float* __restrict__ bbox,
                     const float* __restrict__ W1) {
    int i = blockIdx.x & 31;
    int c = blockIdx.x >> 5;
    int k0 = c * KC;
    int len = KIN - k0; if (len > KC) len = KC;
    __shared__ float seg[KC];
    int tid = threadIdx.x;
    for (int kk = tid; kk < len; kk += 256) {
        int gk = k0 + kk;
        float v;
        if (gk < 4096)      v = roi[i * 4096 + gk];
        else if (gk < 4247) v = logits[i * OC + gk - 4096];
        else                v = bbox[i * 4 + gk - 4247];
        seg[kk] = v;
    }
    __syncthreads();
    const float* Wp = W1 + (long)k0 * DD + tid;
    float a0 = 0.f, a1 = 0.f, a2 = 0.f, a3 = 0.f;
    int kk = 0;
    for (; kk + 4 <= len; kk += 4) {
        a0 += seg[kk]     * Wp[(kk)     * DD];
        a1 += seg[kk + 1] * Wp[(kk + 1) * DD];
        a2 += seg[kk + 2] * Wp[(kk + 2) * DD];
        a3 += seg[kk + 3] * Wp[(kk + 3) * DD];
    }
    for (; kk < len; kk++) a0 += seg[kk] * Wp[kk * DD];
    g_part[blockIdx.x * DD + tid] = (a0 + a1) + (a2 + a3);
}

// ============================================================
// A2: combine partials, relu, GEMM2 -> obj_feats (g_feats rows 0..31)
// ============================================================
__global__ __launch_bounds__(256)
void obj_emb2_kernel(const float* __restrict__ b1,
                     const float* __restrict__ W2,
                     const float* __restrict__ b2) {
    int i = blockIdx.x, tid = threadIdx.x;
    __shared__ float hid[DD];
    float h = b1[tid];
    #pragma unroll
    for (int c = 0; c < 4; c++) h += g_part[(c * NN + i) * DD + tid];
    hid[tid] = fmaxf(h, 0.f);
    __syncthreads();
    float acc = b2[tid];
    #pragma unroll 4
    for (int k = 0; k < DD; k++) acc += hid[k] * W2[k * DD + tid];
    g_feats[i * DD + tid] = acc;
}

// ============================================================
// B: rectangle-mask pooling.  grid = 992 (one pair per block)
// ============================================================
__global__ __launch_bounds__(256)
void mask_mean_kernel(const float* __restrict__ uf,
                      const float* __restrict__ bboxes,
                      const int* __restrict__ pairs) {
    int p = blockIdx.x, tid = threadIdx.x;
    __shared__ int   code[SP2];
    __shared__ float rect[8];
    if (tid == 0) {
        int si = pairs[2 * p], oi = pairs[2 * p + 1];
        float sb0 = bboxes[4 * si],     sb1 = bboxes[4 * si + 1];
        float sb2 = bboxes[4 * si + 2], sb3 = bboxes[4 * si + 3];
        float ob0 = bboxes[4 * oi],     ob1 = bboxes[4 * oi + 1];
        float ob2 = bboxes[4 * oi + 2], ob3 = bboxes[4 * oi + 3];
        float ux = fminf(sb0, ob0), uy = fminf(sb1, ob1);
        float xs0 = sb0 - ux, xs1 = sb2 - ux, xo0 = ob0 - ux, xo1 = ob2 - ux;
        float ys0 = sb1 - uy, ys1 = sb3 - uy, yo0 = ob1 - uy, yo1 = ob3 - uy;
        float xr = 14.f / fmaxf(xs1, xo1);
        float yr = 14.f / fmaxf(ys1, yo1);
        rect[0] = rintf(xs0 * xr); rect[1] = rintf(xs1 * xr);
        rect[2] = rintf(ys0 * yr); rect[3] = rintf(ys1 * yr);
        rect[4] = rintf(xo0 * xr); rect[5] = rintf(xo1 * xr);
        rect[6] = rintf(yo0 * yr); rect[7] = rintf(yo1 * yr);
    }
    __syncthreads();
    if (tid < SP2) {
        float fi = (float)(tid / MM), fj = (float)(tid % MM);
        int c = 0;
        if (fi >= rect[0] && fi < rect[1] && fj >= rect[2] && fj < rect[3]) c |= 1;
        if (fi >= rect[4] && fi < rect[5] && fj >= rect[6] && fj < rect[7]) c |= 2;
        code[tid] = c;
    }
    __syncthreads();
    int warp = tid >> 5, lane = tid & 31;
    for (int d = warp; d < DD; d += 8) {
        const float* base = uf + ((long)p * DD + d) * SP2;
        float ss = 0.f, so = 0.f, sb = 0.f;
        #pragma unroll 2
        for (int e = lane; e < SP2; e += 32) {
            float v = base[e];
            int c = code[e];
            if (c & 1)  ss += v;
            if (c & 2)  so += v;
            if (c == 0) sb += v;
        }
        #pragma unroll
        for (int off = 16; off; off >>= 1) {
            ss += __shfl_xor_sync(0xffffffffu, ss, off);
            so += __shfl_xor_sync(0xffffffffu, so, off);
            sb += __shfl_xor_sync(0xffffffffu, sb, off);
        }
        if (lane == 0) {
            g_sall[p * 768 + d]       = ss / 196.f;
            g_sall[p * 768 + 256 + d] = so / 196.f;
            g_sall[p * 768 + 512 + d] = sb / 196.f;
        }
    }
}

// ============================================================
// C: per-branch SE gate, in-place on g_sall.  grid = (62 row tiles, 3 branches)
// ============================================================
__global__ __launch_bounds__(256)
void gate_kernel(const float* __restrict__ w1a, const float* __restrict__ b1a,
                 const float* __restrict__ w2a, const float* __restrict__ b2a) {
    int b = blockIdx.y;
    int row0 = blockIdx.x * 16;
    int tid = threadIdx.x;
    __shared__ float S[16][DD];
    __shared__ float H[16][RED];
    #pragma unroll
    for (int r = 0; r < 16; r++)
        S[r][tid] = g_sall[(row0 + r) * 768 + b * DD + tid];
    __syncthreads();
    const float* w1 = w1a + b * DD * RED;
    const float* w2 = w2a + b * RED * DD;
    {
        int u = tid & 63;
        float bv = b1a[b * RED + u];
        for (int r = tid >> 6; r < 16; r += 4) {
            float acc = bv;
            #pragma unroll 4
            for (int k = 0; k < DD; k++) acc += S[r][k] * w1[k * RED + u];
            H[r][u] = fmaxf(acc, 0.f);
        }
    }
    __syncthreads();
    float bv2 = b2a[b * DD + tid];
    for (int r = 0; r < 16; r++) {
        float acc = bv2;
        #pragma unroll
        for (int k = 0; k < RED; k++) acc += H[r][k] * w2[k * DD + tid];
        float g = 1.f / (1.f + expf(-acc));
        g_sall[(row0 + r) * 768 + b * DD + tid] = S[r][tid] * g;
    }
}

// ============================================================
// Generic fp32 GEMM: C[M,N] = act(A[M,K] @ B[K,N] + bias)
// BM=32, BN=64, BK=16, 256 threads, 2x4 micro tile, double buffered
// ============================================================
template<int ACT, int BIAS>
__global__ __launch_bounds__(256)
void gemm32x64(const float* __restrict__ A, const float* __restrict__ B,
               const float* __restrict__ bias, float* __restrict__ C,
               int M, int N, int K) {
    __shared__ __align__(16) float As[2][16][34];
    __shared__ __align__(16) float Bs[2][16][64];
    int tid = threadIdx.x;
    int row0 = blockIdx.y * 32, col0 = blockIdx.x * 64;
    int ak = tid & 15, am = tid >> 4;
    int bk = tid >> 6, bc = tid & 63;
    int cg = tid & 15, rg = tid >> 4;
    const float* Aptr  = A + (long)(row0 + am)      * K + ak;
    const float* Aptr2 = A + (long)(row0 + am + 16) * K + ak;
    const float* Bptr  = B + (long)bk * N + col0 + bc;
    int T = K >> 4;
    float ra0, ra1, rb[4];
    ra0 = Aptr[0]; ra1 = Aptr2[0];
    #pragma unroll
    for (int i = 0; i < 4; i++) rb[i] = Bptr[(long)(4 * i) * N];
    As[0][ak][am] = ra0; As[0][ak][am + 16] = ra1;
    #pragma unroll
    for (int i = 0; i < 4; i++) Bs[0][bk + 4 * i][bc] = rb[i];
    __syncthreads();
    float acc[2][4];
    #pragma unroll
    for (int r = 0; r < 2; r++)
        #pragma unroll
        for (int c = 0; c < 4; c++) acc[r][c] = 0.f;
    for (int t = 0; t < T; t++) {
        int cur = t & 1;
        if (t + 1 < T) {
            ra0 = Aptr[(t + 1) * 16];
            ra1 = Aptr2[(t + 1) * 16];
            #pragma unroll
            for (int i = 0; i < 4; i++)
                rb[i] = Bptr[(long)((t + 1) * 16 + 4 * i) * N];
        }
        #pragma unroll
        for (int k = 0; k < 16; k++) {
            float2 a = *(const float2*)&As[cur][k][rg * 2];
            float4 b = *(const float4*)&Bs[cur][k][cg * 4];
            acc[0][0] += a.x * b.x; acc[0][1] += a.x * b.y;
            acc[0][2] += a.x * b.z; acc[0][3] += a.x * b.w;
            acc[1][0] += a.y * b.x; acc[1][1] += a.y * b.y;
            acc[1][2] += a.y * b.z; acc[1][3] += a.y * b.w;
        }
        if (t + 1 < T) {
            int nxt = 1 - cur;
            As[nxt][ak][am] = ra0; As[nxt][ak][am + 16] = ra1;
            #pragma unroll
            for (int i = 0; i < 4; i++) Bs[nxt][bk + 4 * i][bc] = rb[i];
        }
        __syncthreads();
    }
    #pragma unroll
    for (int rr = 0; rr < 2; rr++) {
        int r = row0 + rg * 2 + rr;
        #pragma unroll
        for (int cc = 0; cc < 4; cc++) {
            int c = col0 + cg * 4 + cc;
            float v = acc[rr][cc];
            if (BIAS) v += bias[c];
            if (ACT == 1) v = fmaxf(v, 0.f);
            C[(long)r * N + c] = v;
        }
    }
}

// ============================================================
// G1: GCN object rows + obj_dists.  grid = 32
// FIXED: projection now computes a full 256-k dot per column
// (previous version needed 302 threads but only had 256 ->
//  columns 105..150 of the k-upper-half were never computed).
// ============================================================
__global__ __launch_bounds__(256)
void gcn_obj_kernel(const int* __restrict__ pairs,
                    const float* __restrict__ b_gcn,
                    const float* __restrict__ W_objp,
                    const float* __restrict__ b_objp,
                    float* __restrict__ out) {
    int i = blockIdx.x, tid = threadIdx.x;
    __shared__ int sp[PP * 2];
    __shared__ float row[DD];
    for (int k = tid; k < PP * 2; k += 256) sp[k] = pairs[k];
    __syncthreads();
    float acc = g_h[i * DD + tid];  // eye
    int deg = 1;
    for (int p = 0; p < PP; p++) {
        int s = sp[2 * p], o = sp[2 * p + 1];
        if (s == i) {
            acc += g_h[o * DD + tid];
            acc += g_h[(NN + p) * DD + tid];
            deg += 2;
        } else if (o == i) {
            acc += g_h[(NN + p) * DD + tid];
            deg += 1;
        }
    }
    row[tid] = fmaxf(acc / (float)deg + b_gcn[tid], 0.f) + g_feats[i * DD + tid];
    __syncthreads();
    if (tid < OC) {
        float a = b_objp[tid];
        #pragma unroll 4
        for (int k = 0; k < DD; k++) a += row[k] * W_objp[k * OC + tid];
        out[i * OC + tid] = a;
    }
}

// ============================================================
// G2: GCN relation rows + rel_dists.  grid = 992
// ============================================================
__global__ __launch_bounds__(256)
void gcn_rel_kernel(const int* __restrict__ pairs,
                    const float* __restrict__ b_gcn,
                    const float* __restrict__ W_relp,
                    const float* __restrict__ b_relp,
                    float* __restrict__ out) {
    int p = blockIdx.x, tid = threadIdx.x;
    __shared__ float row[DD];
    __shared__ float ps[4 * RC];
    int s = pairs[2 * p], o = pairs[2 * p + 1];
    float num = g_h[(NN + p) * DD + tid] + g_h[s * DD + tid];
    float deg = 2.f;
    if (s != o) { num += g_h[o * DD + tid]; deg = 3.f; }
    row[tid] = fmaxf(num / deg + b_gcn[tid], 0.f) + g_feats[(NN + p) * DD + tid];
    __syncthreads();
    if (tid < 4 * RC) {
        int c = tid % RC, part = tid / RC;
        float a = 0.f;
        int k0 = part * 64;
        #pragma unroll 4
        for (int k = k0; k < k0 + 64; k++) a += row[k] * W_relp[k * RC + c];
        ps[tid] = a;
    }
    __syncthreads();
    if (tid < RC)
        out[NN * OC + p * RC + tid] =
            b_relp[tid] + ps[tid] + ps[RC + tid] + ps[2 * RC + tid] + ps[3 * RC + tid];
}

// ============================================================
// launch
// ============================================================
extern "C" void kernel_launch(void* const* d_in, const int* in_sizes, int n_in,
                              void* d_out, int out_size) {
    const float* roi     = (const float*)d_in[0];
    const float* bbox    = (const float*)d_in[1];
    const float* logits  = (const float*)d_in[2];
    const float* uf      = (const float*)d_in[3];
    const int*   pairs   = (const int*)  d_in[4];
    const float* W_emb1  = (const float*)d_in[5];
    const float* b_emb1  = (const float*)d_in[6];
    const float* W_emb2  = (const float*)d_in[7];
    const float* b_emb2  = (const float*)d_in[8];
    const float* att1w   = (const float*)d_in[9];
    const float* att1b   = (const float*)d_in[10];
    const float* att2w   = (const float*)d_in[11];
    const float* att2b   = (const float*)d_in[12];
    const float* W_c1    = (const float*)d_in[13];
    const float* b_c1    = (const float*)d_in[14];
    const float* W_c2    = (const float*)d_in[15];
    const float* b_c2    = (const float*)d_in[16];
    const float* W_gcn   = (const float*)d_in[17];
    const float* b_gcn   = (const float*)d_in[18];
    const float* W_objp  = (const float*)d_in[19];
    const float* b_objp  = (const float*)d_in[20];
    const float* W_relp  = (const float*)d_in[21];
    const float* b_relp  = (const float*)d_in[22];
    float* out = (float*)d_out;

    void *p_sall, *p_h1, *p_feats, *p_h;
    cudaGetSymbolAddress(&p_sall,  g_sall);
    cudaGetSymbolAddress(&p_h1,    g_h1);
    cudaGetSymbolAddress(&p_feats, g_feats);
    cudaGetSymbolAddress(&p_h,     g_h);
    float* sall  = (float*)p_sall;
    float* h1    = (float*)p_h1;
    float* feats = (float*)p_feats;
    float* hg    = (float*)p_h;

    // object embedding path
    obj_emb1_kernel<<<128, 256>>>(roi, logits, bbox, W_emb1);
    obj_emb2_kernel<<<NN, 256>>>(b_emb1, W_emb2, b_emb2);

    // union-feature mask pooling (the big DRAM pass)
    mask_mean_kernel<<<PP, 256>>>(uf, bbox, pairs);

    // SE gates (in place on sall)
    gate_kernel<<<dim3(PP / 16, 3), 256>>>(att1w, att1b, att2w, att2b);

    // rel MLP
    gemm32x64<1, 1><<<dim3(4, PP / 32), 256>>>(sall, W_c1, b_c1, h1, PP, DD, 3 * DD);
    gemm32x64<0, 1><<<dim3(4, PP / 32), 256>>>(h1, W_c2, b_c2, feats + NN * DD, PP, DD, DD);

    // GCN: h = feats @ W_gcn
    gemm32x64<0, 0><<<dim3(4, (NN + PP) / 32), 256>>>(feats, W_gcn, b_gcn, hg, NN + PP, DD, DD);

    // GCN aggregate + projections (writes d_out)
    gcn_obj_kernel<<<NN, 256>>>(pairs, b_gcn, W_objp, b_objp, out);
    gcn_rel_kernel<<<PP, 256>>>(pairs, b_gcn, W_relp, b_relp, out);
}

// round 5
// speedup vs baseline: 1.2419x; 1.2419x over previous
#include <cuda_runtime.h>
#include <math.h>

typedef unsigned long long ull;

// ---------------- problem constants ----------------
#define NN   32
#define PP   992
#define DD   256
#define MM   14
#define OC   151
#define RC   51
#define RED  64
#define KIN  4251          // 4096 + 151 + 4
#define KCH  133           // obj-emb K chunk (32 chunks of 133 covers 4256)
#define SP2  196           // 14*14

// ---------------- device scratch ----------------
__device__ float g_part[32 * NN * DD];       // obj-emb split-K partials [kchunk][row][col]
__device__ float g_feats[(NN + PP) * DD];    // [obj_feats ; rel_feats]
__device__ float g_sall[PP * 3 * DD];        // masked means -> gated (in place)
__device__ float g_h1[PP * DD];              // rel MLP hidden
__device__ float g_h[(NN + PP) * DD];        // feats @ W_gcn

// ============================================================
// A1: obj-emb GEMM1, tiled split-K. grid = (4 col tiles, 32 k chunks)
// W1 is read exactly once across the whole grid.
// ============================================================
__global__ __launch_bounds__(256)
void obj_emb1_kernel(const float* __restrict__ roi,
                     const float* __restrict__ logits,
                     const float* __restrict__ bbox,
                     const float* __restrict__ W1) {
    __shared__ float As[KCH][33];          // transposed A chunk [kk][row]
    int t = threadIdx.x;
    int col0 = blockIdx.x * 64;
    int k0 = blockIdx.y * KCH;
    // load A chunk (32 rows x 133 k), zero-fill past KIN
    for (int idx = t; idx < 32 * KCH; idx += 256) {
        int r = idx / KCH, kk = idx - r * KCH;
        int gk = k0 + kk;
        float v = 0.f;
        if (gk < 4096)      v = roi[r * 4096 + gk];
        else if (gk < 4247) v = logits[r * OC + gk - 4096];
        else if (gk < KIN)  v = bbox[r * 4 + gk - 4247];
        As[kk][r] = v;
    }
    __syncthreads();
    int c  = t & 63;
    int rq = t >> 6;                       // uniform per warp
    int col = col0 + c;
    int lenc = KIN - k0; if (lenc > KCH) lenc = KCH;
    float acc[8];
    #pragma unroll
    for (int j = 0; j < 8; j++) acc[j] = 0.f;
    const float* Wp = W1 + (long)k0 * DD + col;
    for (int kk = 0; kk < lenc; kk++) {
        float w = Wp[(long)kk * DD];
        #pragma unroll
        for (int j = 0; j < 8; j++) acc[j] += As[kk][rq * 8 + j] * w;
    }
    #pragma unroll
    for (int j = 0; j < 8; j++)
        g_part[((long)blockIdx.y * 32 + rq * 8 + j) * DD + col] = acc[j];
}

// ============================================================
// A2: reduce partials, relu, GEMM2 -> obj_feats. grid = 32
// ============================================================
__global__ __launch_bounds__(256)
void obj_emb2_kernel(const float* __restrict__ b1,
                     const float* __restrict__ W2,
                     const float* __restrict__ b2) {
    int i = blockIdx.x, tid = threadIdx.x;
    __shared__ float hid[DD];
    float h = b1[tid];
    #pragma unroll 8
    for (int kc = 0; kc < 32; kc++) h += g_part[(kc * 32 + i) * DD + tid];
    hid[tid] = fmaxf(h, 0.f);
    __syncthreads();
    float a0 = b2[tid], a1 = 0.f, a2 = 0.f, a3 = 0.f;
    const float* Wp = W2 + tid;
    #pragma unroll 4
    for (int k = 0; k < DD; k += 4) {
        a0 += hid[k]     * Wp[(k)     * DD];
        a1 += hid[k + 1] * Wp[(k + 1) * DD];
        a2 += hid[k + 2] * Wp[(k + 2) * DD];
        a3 += hid[k + 3] * Wp[(k + 3) * DD];
    }
    g_feats[i * DD + tid] = (a0 + a1) + (a2 + a3);
}

// ============================================================
// B: rectangle-mask pooling.  grid = (992, 2): 128 channels per block
// ============================================================
__global__ __launch_bounds__(256)
void mask_mean_kernel(const float* __restrict__ uf,
                      const float* __restrict__ bboxes,
                      const int* __restrict__ pairs) {
    int p = blockIdx.x, tid = threadIdx.x;
    __shared__ int   code[SP2];
    __shared__ float rect[8];
    if (tid == 0) {
        int si = pairs[2 * p], oi = pairs[2 * p + 1];
        float sb0 = bboxes[4 * si],     sb1 = bboxes[4 * si + 1];
        float sb2 = bboxes[4 * si + 2], sb3 = bboxes[4 * si + 3];
        float ob0 = bboxes[4 * oi],     ob1 = bboxes[4 * oi + 1];
        float ob2 = bboxes[4 * oi + 2], ob3 = bboxes[4 * oi + 3];
        float ux = fminf(sb0, ob0), uy = fminf(sb1, ob1);
        float xs0 = sb0 - ux, xs1 = sb2 - ux, xo0 = ob0 - ux, xo1 = ob2 - ux;
        float ys0 = sb1 - uy, ys1 = sb3 - uy, yo0 = ob1 - uy, yo1 = ob3 - uy;
        float xr = 14.f / fmaxf(xs1, xo1);
        float yr = 14.f / fmaxf(ys1, yo1);
        rect[0] = rintf(xs0 * xr); rect[1] = rintf(xs1 * xr);
        rect[2] = rintf(ys0 * yr); rect[3] = rintf(ys1 * yr);
        rect[4] = rintf(xo0 * xr); rect[5] = rintf(xo1 * xr);
        rect[6] = rintf(yo0 * yr); rect[7] = rintf(yo1 * yr);
    }
    __syncthreads();
    if (tid < SP2) {
        float fi = (float)(tid / MM), fj = (float)(tid % MM);
        int c = 0;
        if (fi >= rect[0] && fi < rect[1] && fj >= rect[2] && fj < rect[3]) c |= 1;
        if (fi >= rect[4] && fi < rect[5] && fj >= rect[6] && fj < rect[7]) c |= 2;
        code[tid] = c;
    }
    __syncthreads();
    int warp = tid >> 5, lane = tid & 31;
    int d0 = blockIdx.y * 128;
    for (int d = d0 + warp; d < d0 + 128; d += 8) {
        const float* base = uf + ((long)p * DD + d) * SP2;
        float ss = 0.f, so = 0.f, sb = 0.f;
        #pragma unroll 7
        for (int e = lane; e < SP2; e += 32) {
            float v = base[e];
            int c = code[e];
            if (c & 1)  ss += v;
            if (c & 2)  so += v;
            if (c == 0) sb += v;
        }
        #pragma unroll
        for (int off = 16; off; off >>= 1) {
            ss += __shfl_xor_sync(0xffffffffu, ss, off);
            so += __shfl_xor_sync(0xffffffffu, so, off);
            sb += __shfl_xor_sync(0xffffffffu, sb, off);
        }
        if (lane == 0) {
            g_sall[p * 768 + d]       = ss / 196.f;
            g_sall[p * 768 + 256 + d] = so / 196.f;
            g_sall[p * 768 + 512 + d] = sb / 196.f;
        }
    }
}

// ============================================================
// C: SE gate, 16 rows/block, grid = (62, 3). ILP-heavy rewrite.
// ============================================================
__global__ __launch_bounds__(256)
void gate_kernel(const float* __restrict__ w1a, const float* __restrict__ b1a,
                 const float* __restrict__ w2a, const float* __restrict__ b2a) {
    int b = blockIdx.y;
    int row0 = blockIdx.x * 16;
    int tid = threadIdx.x;
    __shared__ __align__(16) float S[16][DD];
    __shared__ __align__(16) float H[16][RED];
    #pragma unroll
    for (int r = 0; r < 16; r++)
        S[r][tid] = g_sall[(row0 + r) * 768 + b * DD + tid];
    __syncthreads();
    const float* w1 = w1a + b * DD * RED;
    const float* w2 = w2a + b * RED * DD;
    // stage 1: H[16][64] = relu(S @ w1 + b1); thread = (u, rq) covers 4 rows
    {
        int u = tid & 63, rq = tid >> 6;
        float acc0, acc1, acc2, acc3;
        acc0 = acc1 = acc2 = acc3 = b1a[b * RED + u];
        const float* w1p = w1 + u;
        int r0 = rq * 4;
        for (int k = 0; k < DD; k += 4) {
            float4 s0 = *(const float4*)&S[r0][k];
            float4 s1 = *(const float4*)&S[r0 + 1][k];
            float4 s2 = *(const float4*)&S[r0 + 2][k];
            float4 s3 = *(const float4*)&S[r0 + 3][k];
            float wv0 = w1p[(k)     * RED];
            float wv1 = w1p[(k + 1) * RED];
            float wv2 = w1p[(k + 2) * RED];
            float wv3 = w1p[(k + 3) * RED];
            acc0 += s0.x * wv0 + s0.y * wv1 + s0.z * wv2 + s0.w * wv3;
            acc1 += s1.x * wv0 + s1.y * wv1 + s1.z * wv2 + s1.w * wv3;
            acc2 += s2.x * wv0 + s2.y * wv1 + s2.z * wv2 + s2.w * wv3;
            acc3 += s3.x * wv0 + s3.y * wv1 + s3.z * wv2 + s3.w * wv3;
        }
        H[r0][u]     = fmaxf(acc0, 0.f);
        H[r0 + 1][u] = fmaxf(acc1, 0.f);
        H[r0 + 2][u] = fmaxf(acc2, 0.f);
        H[r0 + 3][u] = fmaxf(acc3, 0.f);
    }
    __syncthreads();
    // stage 2: g = sigmoid(H @ w2 + b2); out = S * g. thread = one col, 16 rows
    {
        int c = tid;
        float acc[16];
        float bv = b2a[b * DD + c];
        #pragma unroll
        for (int r = 0; r < 16; r++) acc[r] = bv;
        const float* w2p = w2 + c;
        for (int k = 0; k < RED; k += 4) {
            float wv0 = w2p[(k)     * DD];
            float wv1 = w2p[(k + 1) * DD];
            float wv2 = w2p[(k + 2) * DD];
            float wv3 = w2p[(k + 3) * DD];
            #pragma unroll
            for (int r = 0; r < 16; r++) {
                float4 hv = *(const float4*)&H[r][k];
                acc[r] += hv.x * wv0 + hv.y * wv1 + hv.z * wv2 + hv.w * wv3;
            }
        }
        #pragma unroll
        for (int r = 0; r < 16; r++) {
            float g = 1.f / (1.f + expf(-acc[r]));
            g_sall[(row0 + r) * 768 + b * DD + c] = S[r][c] * g;
        }
    }
}

// ============================================================
// Generic fp32 GEMM with packed f32x2 FMA:
// C[M,N] = act(A[M,K] @ B[K,N] + bias). BM=32, BN=64, BK=16.
// ============================================================
template<int ACT, int BIAS>
__global__ __launch_bounds__(256)
void gemm32x64(const float* __restrict__ A, const float* __restrict__ B,
               const float* __restrict__ bias, float* __restrict__ C,
               int M, int N, int K) {
    __shared__ __align__(16) float2 As[2][16][34];   // duplicated pairs [k][row]
    __shared__ __align__(16) float  Bs[2][16][64];
    int tid = threadIdx.x;
    int row0 = blockIdx.y * 32, col0 = blockIdx.x * 64;
    int ak = tid & 15, am = tid >> 4;
    int bk = tid >> 6, bc = tid & 63;
    int cg = tid & 15, rg = tid >> 4;
    const float* Aptr  = A + (long)(row0 + am)      * K + ak;
    const float* Aptr2 = A + (long)(row0 + am + 16) * K + ak;
    const float* Bptr  = B + (long)bk * N + col0 + bc;
    int T = K >> 4;
    float ra0, ra1, rb[4];
    ra0 = Aptr[0]; ra1 = Aptr2[0];
    #pragma unroll
    for (int i = 0; i < 4; i++) rb[i] = Bptr[(long)(4 * i) * N];
    As[0][ak][am]      = make_float2(ra0, ra0);
    As[0][ak][am + 16] = make_float2(ra1, ra1);
    #pragma unroll
    for (int i = 0; i < 4; i++) Bs[0][bk + 4 * i][bc] = rb[i];
    __syncthreads();
    ull acc00 = 0ull, acc01 = 0ull, acc10 = 0ull, acc11 = 0ull; // {r0c01,r0c23,r1c01,r1c23}
    for (int t = 0; t < T; t++) {
        int cur = t & 1;
        if (t + 1 < T) {
            ra0 = Aptr[(t + 1) * 16];
            ra1 = Aptr2[(t + 1) * 16];
            #pragma unroll
            for (int i = 0; i < 4; i++)
                rb[i] = Bptr[(long)((t + 1) * 16 + 4 * i) * N];
        }
        #pragma unroll
        for (int k = 0; k < 16; k++) {
            ull a0 = *(const ull*)&As[cur][k][rg * 2];
            ull a1 = *(const ull*)&As[cur][k][rg * 2 + 1];
            ulonglong2 bb = *(const ulonglong2*)&Bs[cur][k][cg * 4];
            asm("fma.rn.f32x2 %0, %1, %2, %0;" : "+l"(acc00) : "l"(a0), "l"(bb.x));
            asm("fma.rn.f32x2 %0, %1, %2, %0;" : "+l"(acc01) : "l"(a0), "l"(bb.y));
            asm("fma.rn.f32x2 %0, %1, %2, %0;" : "+l"(acc10) : "l"(a1), "l"(bb.x));
            asm("fma.rn.f32x2 %0, %1, %2, %0;" : "+l"(acc11) : "l"(a1), "l"(bb.y));
        }
        if (t + 1 < T) {
            int nxt = 1 - cur;
            As[nxt][ak][am]      = make_float2(ra0, ra0);
            As[nxt][ak][am + 16] = make_float2(ra1, ra1);
            #pragma unroll
            for (int i = 0; i < 4; i++) Bs[nxt][bk + 4 * i][bc] = rb[i];
        }
        __syncthreads();
    }
    float vals[2][4];
    {
        float2 t0 = *(float2*)&acc00, t1 = *(float2*)&acc01;
        float2 t2 = *(float2*)&acc10, t3 = *(float2*)&acc11;
        vals[0][0] = t0.x; vals[0][1] = t0.y; vals[0][2] = t1.x; vals[0][3] = t1.y;
        vals[1][0] = t2.x; vals[1][1] = t2.y; vals[1][2] = t3.x; vals[1][3] = t3.y;
    }
    #pragma unroll
    for (int rr = 0; rr < 2; rr++) {
        int r = row0 + rg * 2 + rr;
        #pragma unroll
        for (int cc = 0; cc < 4; cc++) {
            int c = col0 + cg * 4 + cc;
            float v = vals[rr][cc];
            if (BIAS) v += bias[c];
            if (ACT == 1) v = fmaxf(v, 0.f);
            C[(long)r * N + c] = v;
        }
    }
}

// ============================================================
// G: fused GCN aggregate + projections. grid = 1024
//    blocks 0..31 -> object rows, 32..1023 -> relation rows
// ============================================================
__global__ __launch_bounds__(256)
void gcn_fused_kernel(const int* __restrict__ pairs,
                      const float* __restrict__ b_gcn,
                      const float* __restrict__ W_objp,
                      const float* __restrict__ b_objp,
                      const float* __restrict__ W_relp,
                      const float* __restrict__ b_relp,
                      float* __restrict__ out) {
    int tid = threadIdx.x;
    if (blockIdx.x < NN) {
        int i = blockIdx.x;
        __shared__ int sp[PP * 2];
        __shared__ float row[DD];
        for (int k = tid; k < PP * 2; k += 256) sp[k] = pairs[k];
        __syncthreads();
        float acc = g_h[i * DD + tid];  // eye
        int deg = 1;
        for (int p = 0; p < PP; p++) {
            int s = sp[2 * p], o = sp[2 * p + 1];
            if (s == i) {
                acc += g_h[o * DD + tid];
                acc += g_h[(NN + p) * DD + tid];
                deg += 2;
            } else if (o == i) {
                acc += g_h[(NN + p) * DD + tid];
                deg += 1;
            }
        }
        row[tid] = fmaxf(acc / (float)deg + b_gcn[tid], 0.f) + g_feats[i * DD + tid];
        __syncthreads();
        if (tid < OC) {
            float a0 = b_objp[tid], a1 = 0.f, a2 = 0.f, a3 = 0.f;
            const float* Wp = W_objp + tid;
            #pragma unroll 4
            for (int k = 0; k < DD; k += 4) {
                a0 += row[k]     * Wp[(k)     * OC];
                a1 += row[k + 1] * Wp[(k + 1) * OC];
                a2 += row[k + 2] * Wp[(k + 2) * OC];
                a3 += row[k + 3] * Wp[(k + 3) * OC];
            }
            out[i * OC + tid] = (a0 + a1) + (a2 + a3);
        }
    } else {
        int p = blockIdx.x - NN;
        __shared__ float row[DD];
        __shared__ float ps[4 * RC];
        int s = pairs[2 * p], o = pairs[2 * p + 1];
        float num = g_h[(NN + p) * DD + tid] + g_h[s * DD + tid];
        float deg = 2.f;
        if (s != o) { num += g_h[o * DD + tid]; deg = 3.f; }
        row[tid] = fmaxf(num / deg + b_gcn[tid], 0.f) + g_feats[(NN + p) * DD + tid];
        __syncthreads();
        if (tid < 4 * RC) {
            int c = tid % RC, part = tid / RC;
            float a = 0.f;
            int k0 = part * 64;
            #pragma unroll 4
            for (int k = k0; k < k0 + 64; k++) a += row[k] * W_relp[k * RC + c];
            ps[tid] = a;
        }
        __syncthreads();
        if (tid < RC)
            out[NN * OC + p * RC + tid] =
                b_relp[tid] + ps[tid] + ps[RC + tid] + ps[2 * RC + tid] + ps[3 * RC + tid];
    }
}

// ============================================================
// launch
// ============================================================
extern "C" void kernel_launch(void* const* d_in, const int* in_sizes, int n_in,
                              void* d_out, int out_size) {
    const float* roi     = (const float*)d_in[0];
    const float* bbox    = (const float*)d_in[1];
    const float* logits  = (const float*)d_in[2];
    const float* uf      = (const float*)d_in[3];
    const int*   pairs   = (const int*)  d_in[4];
    const float* W_emb1  = (const float*)d_in[5];
    const float* b_emb1  = (const float*)d_in[6];
    const float* W_emb2  = (const float*)d_in[7];
    const float* b_emb2  = (const float*)d_in[8];
    const float* att1w   = (const float*)d_in[9];
    const float* att1b   = (const float*)d_in[10];
    const float* att2w   = (const float*)d_in[11];
    const float* att2b   = (const float*)d_in[12];
    const float* W_c1    = (const float*)d_in[13];
    const float* b_c1    = (const float*)d_in[14];
    const float* W_c2    = (const float*)d_in[15];
    const float* b_c2    = (const float*)d_in[16];
    const float* W_gcn   = (const float*)d_in[17];
    const float* b_gcn   = (const float*)d_in[18];
    const float* W_objp  = (const float*)d_in[19];
    const float* b_objp  = (const float*)d_in[20];
    const float* W_relp  = (const float*)d_in[21];
    const float* b_relp  = (const float*)d_in[22];
    float* out = (float*)d_out;

    void *p_sall, *p_h1, *p_feats, *p_h;
    cudaGetSymbolAddress(&p_sall,  g_sall);
    cudaGetSymbolAddress(&p_h1,    g_h1);
    cudaGetSymbolAddress(&p_feats, g_feats);
    cudaGetSymbolAddress(&p_h,     g_h);
    float* sall  = (float*)p_sall;
    float* h1    = (float*)p_h1;
    float* feats = (float*)p_feats;
    float* hg    = (float*)p_h;

    // object embedding path
    obj_emb1_kernel<<<dim3(4, 32), 256>>>(roi, logits, bbox, W_emb1);
    obj_emb2_kernel<<<NN, 256>>>(b_emb1, W_emb2, b_emb2);

    // union-feature mask pooling (the big DRAM pass)
    mask_mean_kernel<<<dim3(PP, 2), 256>>>(uf, bbox, pairs);

    // SE gates (in place on sall)
    gate_kernel<<<dim3(62, 3), 256>>>(att1w, att1b, att2w, att2b);

    // rel MLP
    gemm32x64<1, 1><<<dim3(4, PP / 32), 256>>>(sall, W_c1, b_c1, h1, PP, DD, 3 * DD);
    gemm32x64<0, 1><<<dim3(4, PP / 32), 256>>>(h1, W_c2, b_c2, feats + NN * DD, PP, DD, DD);

    // GCN: h = feats @ W_gcn
    gemm32x64<0, 0><<<dim3(4, (NN + PP) / 32), 256>>>(feats, W_gcn, b_gcn, hg, NN + PP, DD, DD);

    // GCN aggregate + projections (writes d_out)
    gcn_fused_kernel<<<NN + PP, 256>>>(pairs, b_gcn, W_objp, b_objp, W_relp, b_relp, out);
}

// round 6
// speedup vs baseline: 1.4201x; 1.1435x over previous
#include <cuda_runtime.h>
#include <math.h>

typedef unsigned long long ull;

// ---------------- problem constants ----------------
#define NN   32
#define PP   992
#define DD   256
#define MM   14
#define OC   151
#define RC   51
#define RED  64
#define KIN  4251          // 4096 + 151 + 4
#define KCH  133           // obj-emb K chunk (32 chunks of 133 covers 4256)
#define SP2  196           // 14*14

// ---------------- device scratch ----------------
__device__ float g_part[32 * NN * DD];       // obj-emb split-K partials [kchunk][row][col]
__device__ float g_feats[(NN + PP) * DD];    // [obj_feats ; rel_feats]
__device__ float g_sall[PP * 3 * DD];        // masked means -> gated (in place)
__device__ float g_hb[3 * PP * RED];         // gate hidden per branch
__device__ float g_h1[PP * DD];              // rel MLP hidden
__device__ float g_h[(NN + PP) * DD];        // feats @ W_gcn

// ============================================================
// Generic 32x64 GEMM tile, f32x2 packed FMA, double-buffered.
// C[row0:+32, col0:+64] = epi(A[row0:+32, :K] @ B[:K, col0:+64])
// ldb == N of B. ACT: 0 none, 1 relu, 2 sigmoid*Mul (in-place gate).
// K % 16 == 0. Called with 256 threads.
// ============================================================
__device__ __forceinline__ void gemm_tile32x64(
    const float* __restrict__ A, int lda,
    const float* __restrict__ B, int ldb,
    const float* __restrict__ bias,
    float* __restrict__ C, int ldc,
    const float* __restrict__ Mul, int ldm,
    int row0, int col0, int K, int ACT, int BIAS)
{
    __shared__ __align__(16) float2 As[2][16][34];
    __shared__ __align__(16) float  Bs[2][16][64];
    int tid = threadIdx.x;
    int ak = tid & 15, am = tid >> 4;
    int bk = tid >> 6, bc = tid & 63;
    int cg = tid & 15, rg = tid >> 4;
    const float* Aptr  = A + (long)(row0 + am)      * lda + ak;
    const float* Aptr2 = A + (long)(row0 + am + 16) * lda + ak;
    const float* Bptr  = B + (long)bk * ldb + col0 + bc;
    int T = K >> 4;
    float ra0, ra1, rb[4];
    ra0 = Aptr[0]; ra1 = Aptr2[0];
    #pragma unroll
    for (int i = 0; i < 4; i++) rb[i] = Bptr[(long)(4 * i) * ldb];
    As[0][ak][am]      = make_float2(ra0, ra0);
    As[0][ak][am + 16] = make_float2(ra1, ra1);
    #pragma unroll
    for (int i = 0; i < 4; i++) Bs[0][bk + 4 * i][bc] = rb[i];
    __syncthreads();
    ull acc00 = 0ull, acc01 = 0ull, acc10 = 0ull, acc11 = 0ull;
    for (int t = 0; t < T; t++) {
        int cur = t & 1;
        if (t + 1 < T) {
            ra0 = Aptr[(t + 1) * 16];
            ra1 = Aptr2[(t + 1) * 16];
            #pragma unroll
            for (int i = 0; i < 4; i++)
                rb[i] = Bptr[(long)((t + 1) * 16 + 4 * i) * ldb];
        }
        #pragma unroll
        for (int k = 0; k < 16; k++) {
            ull a0 = *(const ull*)&As[cur][k][rg * 2];
            ull a1 = *(const ull*)&As[cur][k][rg * 2 + 1];
            ulonglong2 bb = *(const ulonglong2*)&Bs[cur][k][cg * 4];
            asm("fma.rn.f32x2 %0, %1, %2, %0;" : "+l"(acc00) : "l"(a0), "l"(bb.x));
            asm("fma.rn.f32x2 %0, %1, %2, %0;" : "+l"(acc01) : "l"(a0), "l"(bb.y));
            asm("fma.rn.f32x2 %0, %1, %2, %0;" : "+l"(acc10) : "l"(a1), "l"(bb.x));
            asm("fma.rn.f32x2 %0, %1, %2, %0;" : "+l"(acc11) : "l"(a1), "l"(bb.y));
        }
        if (t + 1 < T) {
            int nxt = 1 - cur;
            As[nxt][ak][am]      = make_float2(ra0, ra0);
            As[nxt][ak][am + 16] = make_float2(ra1, ra1);
            #pragma unroll
            for (int i = 0; i < 4; i++) Bs[nxt][bk + 4 * i][bc] = rb[i];
        }
        __syncthreads();
    }
    float vals[2][4];
    {
        float2 t0 = *(float2*)&acc00, t1 = *(float2*)&acc01;
        float2 t2 = *(float2*)&acc10, t3 = *(float2*)&acc11;
        vals[0][0] = t0.x; vals[0][1] = t0.y; vals[0][2] = t1.x; vals[0][3] = t1.y;
        vals[1][0] = t2.x; vals[1][1] = t2.y; vals[1][2] = t3.x; vals[1][3] = t3.y;
    }
    #pragma unroll
    for (int rr = 0; rr < 2; rr++) {
        int r = row0 + rg * 2 + rr;
        #pragma unroll
        for (int cc = 0; cc < 4; cc++) {
            int c = col0 + cg * 4 + cc;
            float v = vals[rr][cc];
            if (BIAS) v += bias[c - col0 + col0]; // bias indexed by c
            if (ACT == 1) v = fmaxf(v, 0.f);
            else if (ACT == 2) {
                float g = 1.f / (1.f + expf(-v));
                v = Mul[(long)r * ldm + c] * g;
            }
            C[(long)r * ldc + c] = v;
        }
    }
}

// ============================================================
// K1: blocks 0..127 -> obj-emb GEMM1 split-K; blocks 128..2111 -> mask pooling
// ============================================================
__global__ __launch_bounds__(256)
void k1_mask_emb1(const float* __restrict__ roi,
                  const float* __restrict__ logits,
                  const float* __restrict__ bbox,
                  const float* __restrict__ W1,
                  const float* __restrict__ uf,
                  const int* __restrict__ pairs) {
    int bx = blockIdx.x;
    int t = threadIdx.x;
    if (bx < 128) {
        // ---- obj_emb1: colTile = bx&3, kchunk = bx>>2 ----
        __shared__ float Ae[KCH][33];
        int col0 = (bx & 3) * 64;
        int k0 = (bx >> 2) * KCH;
        for (int idx = t; idx < 32 * KCH; idx += 256) {
            int r = idx / KCH, kk = idx - r * KCH;
            int gk = k0 + kk;
            float v = 0.f;
            if (gk < 4096)      v = roi[r * 4096 + gk];
            else if (gk < 4247) v = logits[r * OC + gk - 4096];
            else if (gk < KIN)  v = bbox[r * 4 + gk - 4247];
            Ae[kk][r] = v;
        }
        __syncthreads();
        int c  = t & 63;
        int rq = t >> 6;
        int col = col0 + c;
        int lenc = KIN - k0; if (lenc > KCH) lenc = KCH;
        float acc[8];
        #pragma unroll
        for (int j = 0; j < 8; j++) acc[j] = 0.f;
        const float* Wp = W1 + (long)k0 * DD + col;
        for (int kk = 0; kk < lenc; kk++) {
            float w = Wp[(long)kk * DD];
            #pragma unroll
            for (int j = 0; j < 8; j++) acc[j] += Ae[kk][rq * 8 + j] * w;
        }
        #pragma unroll
        for (int j = 0; j < 8; j++)
            g_part[((long)(bx >> 2) * 32 + rq * 8 + j) * DD + col] = acc[j];
        return;
    }
    // ---- mask pooling: m = bx-128; p = m>>1; half = m&1 ----
    int m = bx - 128;
    int p = m >> 1;
    __shared__ int   code[SP2];
    __shared__ float rect[8];
    if (t == 0) {
        int si = pairs[2 * p], oi = pairs[2 * p + 1];
        float sb0 = bbox ? 0.f : 0.f; (void)sb0;
    }
    // recompute rects (bboxes pointer passed as 'bbox')
    if (t == 0) {
        int si = pairs[2 * p], oi = pairs[2 * p + 1];
        float s0 = bbox[4 * si],     s1 = bbox[4 * si + 1];
        float s2 = bbox[4 * si + 2], s3 = bbox[4 * si + 3];
        float o0 = bbox[4 * oi],     o1 = bbox[4 * oi + 1];
        float o2 = bbox[4 * oi + 2], o3 = bbox[4 * oi + 3];
        float ux = fminf(s0, o0), uy = fminf(s1, o1);
        float xs0 = s0 - ux, xs1 = s2 - ux, xo0 = o0 - ux, xo1 = o2 - ux;
        float ys0 = s1 - uy, ys1 = s3 - uy, yo0 = o1 - uy, yo1 = o3 - uy;
        float xr = 14.f / fmaxf(xs1, xo1);
        float yr = 14.f / fmaxf(ys1, yo1);
        rect[0] = rintf(xs0 * xr); rect[1] = rintf(xs1 * xr);
        rect[2] = rintf(ys0 * yr); rect[3] = rintf(ys1 * yr);
        rect[4] = rintf(xo0 * xr); rect[5] = rintf(xo1 * xr);
        rect[6] = rintf(yo0 * yr); rect[7] = rintf(yo1 * yr);
    }
    __syncthreads();
    if (t < SP2) {
        float fi = (float)(t / MM), fj = (float)(t % MM);
        int c = 0;
        if (fi >= rect[0] && fi < rect[1] && fj >= rect[2] && fj < rect[3]) c |= 1;
        if (fi >= rect[4] && fi < rect[5] && fj >= rect[6] && fj < rect[7]) c |= 2;
        code[t] = c;
    }
    __syncthreads();
    int warp = t >> 5, lane = t & 31;
    int d0 = (m & 1) * 128;
    for (int d = d0 + warp; d < d0 + 128; d += 8) {
        const float* base = uf + ((long)p * DD + d) * SP2;
        float ss = 0.f, so = 0.f, sb = 0.f;
        #pragma unroll 7
        for (int e = lane; e < SP2; e += 32) {
            float v = base[e];
            int c = code[e];
            if (c & 1)  ss += v;
            if (c & 2)  so += v;
            if (c == 0) sb += v;
        }
        #pragma unroll
        for (int off = 16; off; off >>= 1) {
            ss += __shfl_xor_sync(0xffffffffu, ss, off);
            so += __shfl_xor_sync(0xffffffffu, so, off);
            sb += __shfl_xor_sync(0xffffffffu, sb, off);
        }
        if (lane == 0) {
            g_sall[p * 768 + d]       = ss / 196.f;
            g_sall[p * 768 + 256 + d] = so / 196.f;
            g_sall[p * 768 + 512 + d] = sb / 196.f;
        }
    }
}

// ============================================================
// K2: blocks 0..92 -> gate stage1 GEMM (H = relu(S@w1+b1), 3 branches)
//     blocks 93..220 -> obj_emb2 (32 objs x 4 col chunks)
// ============================================================
__global__ __launch_bounds__(256)
void k2_gateA_emb2(const float* __restrict__ w1a, const float* __restrict__ b1a,
                   const float* __restrict__ b_emb1,
                   const float* __restrict__ W2, const float* __restrict__ b2e) {
    int bx = blockIdx.x;
    int t = threadIdx.x;
    if (bx < 93) {
        int z = bx / 31;
        int row0 = (bx % 31) * 32;
        gemm_tile32x64(g_sall + z * 256, 768,
                       w1a + (long)z * DD * RED, RED,
                       b1a + z * RED,
                       g_hb + (long)z * PP * RED, RED,
                       (const float*)0, 0,
                       row0, 0, DD, 1, 1);
        return;
    }
    // ---- obj_emb2: j = bx-93; i = j>>2; colchunk = j&3 ----
    int j = bx - 93;
    int i = j >> 2, cq = j & 3;
    __shared__ float hid[DD];
    __shared__ float red[4][64];
    {
        float acc = b_emb1[t];
        #pragma unroll 8
        for (int kc = 0; kc < 32; kc++) acc += g_part[(kc * 32 + i) * DD + t];
        hid[t] = fmaxf(acc, 0.f);
    }
    __syncthreads();
    {
        int u = cq * 64 + (t & 63);
        int kq = t >> 6;
        float a0 = 0.f, a1 = 0.f;
        const float* Wp = W2 + u;
        int k0 = kq * 64;
        #pragma unroll 8
        for (int k = k0; k < k0 + 64; k += 2) {
            a0 += hid[k]     * Wp[(k)     * DD];
            a1 += hid[k + 1] * Wp[(k + 1) * DD];
        }
        red[kq][t & 63] = a0 + a1;
    }
    __syncthreads();
    if (t < 64) {
        int u = cq * 64 + t;
        g_feats[i * DD + u] = b2e[u] + red[0][t] + red[1][t] + red[2][t] + red[3][t];
    }
}

// ============================================================
// K3: gate stage2 GEMM: g_sall *= sigmoid(H@w2+b2), 3 branches, in place
// grid = 372 (31 row tiles x 4 col tiles x 3 branches)
// ============================================================
__global__ __launch_bounds__(256)
void k3_gateB(const float* __restrict__ w2a, const float* __restrict__ b2a) {
    int bx = blockIdx.x;
    int z = bx / 124;
    int rem = bx % 124;
    int row0 = (rem >> 2) * 32;
    int col0 = (rem & 3) * 64;
    gemm_tile32x64(g_hb + (long)z * PP * RED, RED,
                   w2a + (long)z * RED * DD, DD,
                   b2a + z * DD,
                   g_sall + z * 256, 768,
                   g_sall + z * 256, 768,
                   row0, col0, RED, 2, 1);
}

// ============================================================
// K4/K5/K6: generic GEMM wrapper
// ============================================================
template<int ACT, int BIAS>
__global__ __launch_bounds__(256)
void gemm_kernel(const float* __restrict__ A, int lda,
                 const float* __restrict__ B, int ldb,
                 const float* __restrict__ bias,
                 float* __restrict__ C, int ldc,
                 int K, int colTiles) {
    int bx = blockIdx.x;
    int row0 = (bx / colTiles) * 32;
    int col0 = (bx % colTiles) * 64;
    gemm_tile32x64(A, lda, B, ldb, bias, C, ldc, (const float*)0, 0,
                   row0, col0, K, ACT, BIAS);
}

// ============================================================
// K7: fused GCN aggregate + projections. grid = 1024
// ============================================================
__global__ __launch_bounds__(256)
void gcn_fused_kernel(const int* __restrict__ pairs,
                      const float* __restrict__ b_gcn,
                      const float* __restrict__ W_objp,
                      const float* __restrict__ b_objp,
                      const float* __restrict__ W_relp,
                      const float* __restrict__ b_relp,
                      float* __restrict__ out) {
    int tid = threadIdx.x;
    if (blockIdx.x < NN) {
        int i = blockIdx.x;
        __shared__ int sp[PP * 2];
        __shared__ float row[DD];
        for (int k = tid; k < PP * 2; k += 256) sp[k] = pairs[k];
        __syncthreads();
        float acc = g_h[i * DD + tid];  // eye
        int deg = 1;
        for (int p = 0; p < PP; p++) {
            int s = sp[2 * p], o = sp[2 * p + 1];
            if (s == i) {
                acc += g_h[o * DD + tid];
                acc += g_h[(NN + p) * DD + tid];
                deg += 2;
            } else if (o == i) {
                acc += g_h[(NN + p) * DD + tid];
                deg += 1;
            }
        }
        row[tid] = fmaxf(acc / (float)deg + b_gcn[tid], 0.f) + g_feats[i * DD + tid];
        __syncthreads();
        if (tid < OC) {
            float a0 = b_objp[tid], a1 = 0.f, a2 = 0.f, a3 = 0.f;
            const float* Wp = W_objp + tid;
            #pragma unroll 4
            for (int k = 0; k < DD; k += 4) {
                a0 += row[k]     * Wp[(k)     * OC];
                a1 += row[k + 1] * Wp[(k + 1) * OC];
                a2 += row[k + 2] * Wp[(k + 2) * OC];
                a3 += row[k + 3] * Wp[(k + 3) * OC];
            }
            out[i * OC + tid] = (a0 + a1) + (a2 + a3);
        }
    } else {
        int p = blockIdx.x - NN;
        __shared__ float row[DD];
        __shared__ float ps[4 * RC];
        int s = pairs[2 * p], o = pairs[2 * p + 1];
        float num = g_h[(NN + p) * DD + tid] + g_h[s * DD + tid];
        float deg = 2.f;
        if (s != o) { num += g_h[o * DD + tid]; deg = 3.f; }
        row[tid] = fmaxf(num / deg + b_gcn[tid], 0.f) + g_feats[(NN + p) * DD + tid];
        __syncthreads();
        if (tid < 4 * RC) {
            int c = tid % RC, part = tid / RC;
            float a = 0.f;
            int k0 = part * 64;
            #pragma unroll 4
            for (int k = k0; k < k0 + 64; k++) a += row[k] * W_relp[k * RC + c];
            ps[tid] = a;
        }
        __syncthreads();
        if (tid < RC)
            out[NN * OC + p * RC + tid] =
                b_relp[tid] + ps[tid] + ps[RC + tid] + ps[2 * RC + tid] + ps[3 * RC + tid];
    }
}

// ============================================================
// launch
// ============================================================
extern "C" void kernel_launch(void* const* d_in, const int* in_sizes, int n_in,
                              void* d_out, int out_size) {
    const float* roi     = (const float*)d_in[0];
    const float* bbox    = (const float*)d_in[1];
    const float* logits  = (const float*)d_in[2];
    const float* uf      = (const float*)d_in[3];
    const int*   pairs   = (const int*)  d_in[4];
    const float* W_emb1  = (const float*)d_in[5];
    const float* b_emb1  = (const float*)d_in[6];
    const float* W_emb2  = (const float*)d_in[7];
    const float* b_emb2  = (const float*)d_in[8];
    const float* att1w   = (const float*)d_in[9];
    const float* att1b   = (const float*)d_in[10];
    const float* att2w   = (const float*)d_in[11];
    const float* att2b   = (const float*)d_in[12];
    const float* W_c1    = (const float*)d_in[13];
    const float* b_c1    = (const float*)d_in[14];
    const float* W_c2    = (const float*)d_in[15];
    const float* b_c2    = (const float*)d_in[16];
    const float* W_gcn   = (const float*)d_in[17];
    const float* b_gcn   = (const float*)d_in[18];
    const float* W_objp  = (const float*)d_in[19];
    const float* b_objp  = (const float*)d_in[20];
    const float* W_relp  = (const float*)d_in[21];
    const float* b_relp  = (const float*)d_in[22];
    float* out = (float*)d_out;

    void *p_sall, *p_h1, *p_feats, *p_h;
    cudaGetSymbolAddress(&p_sall,  g_sall);
    cudaGetSymbolAddress(&p_h1,    g_h1);
    cudaGetSymbolAddress(&p_feats, g_feats);
    cudaGetSymbolAddress(&p_h,     g_h);
    float* sall  = (float*)p_sall;
    float* h1    = (float*)p_h1;
    float* feats = (float*)p_feats;
    float* hg    = (float*)p_h;

    // K1: obj-emb GEMM1 (blocks 0..127, starts first) + mask pooling
    k1_mask_emb1<<<128 + 2 * PP, 256>>>(roi, logits, bbox, W_emb1, uf, pairs);

    // K2: gate stage1 (93 gemm tiles) + obj_emb2 (128 blocks)
    k2_gateA_emb2<<<93 + 128, 256>>>(att1w, att1b, b_emb1, W_emb2, b_emb2);

    // K3: gate stage2, sigmoid * S in place
    k3_gateB<<<372, 256>>>(att2w, att2b);

    // K4: rel MLP layer 1: h1 = relu(sall @ W_c1 + b_c1)   [992 x 768 -> 256]
    gemm_kernel<1, 1><<<124, 256>>>(sall, 768, W_c1, DD, b_c1, h1, DD, 768, 4);

    // K5: rel MLP layer 2: rel_feats = h1 @ W_c2 + b_c2
    gemm_kernel<0, 1><<<124, 256>>>(h1, DD, W_c2, DD, b_c2, feats + NN * DD, DD, DD, 4);

    // K6: GCN: h = feats @ W_gcn   [1024 x 256 -> 256]
    gemm_kernel<0, 0><<<128, 256>>>(feats, DD, W_gcn, DD, (const float*)0, hg, DD, DD, 4);

    // K7: GCN aggregate + projections (writes d_out)
    gcn_fused_kernel<<<NN + PP, 256>>>(pairs, b_gcn, W_objp, b_objp, W_relp, b_relp, out);
}

// round 7
// speedup vs baseline: 1.6966x; 1.1947x over previous
#include <cuda_runtime.h>
#include <math.h>

typedef unsigned long long ull;

// ---------------- problem constants ----------------
#define NN   32
#define PP   992
#define DD   256
#define MM   14
#define OC   151
#define RC   51
#define RED  64
#define KIN  4251
#define KCH  133
#define SP2  196

// ---------------- device scratch ----------------
__device__ float g_part[32 * NN * DD];        // obj-emb split-K partials
__device__ float g_feats[NN * DD];            // obj feats only
__device__ float g_sall[PP * 3 * DD];         // masked means -> gated (in place)
__device__ float g_hbp[2 * 3 * PP * RED];     // gateA partials [split][branch][...]
__device__ float g_h1p[2 * PP * DD];          // rel MLP1 partials
__device__ float g_fq[2 * PP * DD];           // rel MLP2 partials (rel_feats halves)
__device__ float g_hr[2 * (NN + PP) * DD];    // GCN-h partials

// ============================================================
// A-tile loader modes
//  CM 0: plain A0
//  CM 1: relu(A0 + A1 + bA[k])
//  CM 2: row<32 ? g_feats : (A0 + A1 + bA[k]) with rel index r-32
// ============================================================
template<int CM>
__device__ __forceinline__ float4 loadA(const float* __restrict__ A0,
                                        const float* __restrict__ A1,
                                        const float* __restrict__ bA,
                                        int lda, int r, int k) {
    if (CM == 0) {
        return *(const float4*)(A0 + (long)r * lda + k);
    } else if (CM == 1) {
        float4 x = *(const float4*)(A0 + (long)r * lda + k);
        float4 y = *(const float4*)(A1 + (long)r * lda + k);
        float4 b = *(const float4*)(bA + k);
        return make_float4(fmaxf(x.x + y.x + b.x, 0.f),
                           fmaxf(x.y + y.y + b.y, 0.f),
                           fmaxf(x.z + y.z + b.z, 0.f),
                           fmaxf(x.w + y.w + b.w, 0.f));
    } else {
        if (r < NN) return *(const float4*)(g_feats + r * DD + k);
        float4 x = *(const float4*)(A0 + (long)(r - NN) * lda + k);
        float4 y = *(const float4*)(A1 + (long)(r - NN) * lda + k);
        float4 b = *(const float4*)(bA + k);
        return make_float4(x.x + y.x + b.x, x.y + y.y + b.y,
                           x.z + y.z + b.z, x.w + y.w + b.w);
    }
}

// ============================================================
// GEMM tile v2: 32x64, BK=32, scalar-A smem + f32x2 pack, double buffered.
// ACT: 0 none, 1 relu, 2 sigmoid*Mul. 256 threads.
// ============================================================
template<int CM, int ACT, int BIAS>
__device__ __forceinline__ void gemm_tile_v2(
    const float* __restrict__ A0, const float* __restrict__ A1,
    const float* __restrict__ bA, int lda,
    const float* __restrict__ B, int ldb,
    const float* __restrict__ bias,
    float* __restrict__ C, int ldc,
    int row0, int col0, int K, int k0)
{
    __shared__ float As[2][32][33];
    __shared__ __align__(16) float Bs[2][32][64];
    int tid = threadIdx.x;
    int ar = tid >> 3, akq = (tid & 7) * 4;
    int bkb = tid >> 4, bcb = (tid & 15) * 4;
    int cg = tid & 15, rg = tid >> 4;
    int T = K >> 5;
    float4 a4  = loadA<CM>(A0, A1, bA, lda, row0 + ar, k0 + akq);
    float4 b4a = *(const float4*)(B + (long)(k0 + bkb)      * ldb + col0 + bcb);
    float4 b4b = *(const float4*)(B + (long)(k0 + bkb + 16) * ldb + col0 + bcb);
    As[0][akq + 0][ar] = a4.x; As[0][akq + 1][ar] = a4.y;
    As[0][akq + 2][ar] = a4.z; As[0][akq + 3][ar] = a4.w;
    *(float4*)&Bs[0][bkb][bcb]      = b4a;
    *(float4*)&Bs[0][bkb + 16][bcb] = b4b;
    __syncthreads();
    ull acc00 = 0ull, acc01 = 0ull, acc10 = 0ull, acc11 = 0ull;
    for (int t = 0; t < T; t++) {
        int cur = t & 1;
        if (t + 1 < T) {
            int kk = k0 + (t + 1) * 32;
            a4  = loadA<CM>(A0, A1, bA, lda, row0 + ar, kk + akq);
            b4a = *(const float4*)(B + (long)(kk + bkb)      * ldb + col0 + bcb);
            b4b = *(const float4*)(B + (long)(kk + bkb + 16) * ldb + col0 + bcb);
        }
        #pragma unroll
        for (int k = 0; k < 32; k++) {
            float a0s = As[cur][k][rg * 2];
            float a1s = As[cur][k][rg * 2 + 1];
            ull a0d, a1d;
            asm("mov.b64 %0, {%1, %1};" : "=l"(a0d) : "r"(__float_as_uint(a0s)));
            asm("mov.b64 %0, {%1, %1};" : "=l"(a1d) : "r"(__float_as_uint(a1s)));
            ulonglong2 bb = *(const ulonglong2*)&Bs[cur][k][cg * 4];
            asm("fma.rn.f32x2 %0, %1, %2, %0;" : "+l"(acc00) : "l"(a0d), "l"(bb.x));
            asm("fma.rn.f32x2 %0, %1, %2, %0;" : "+l"(acc01) : "l"(a0d), "l"(bb.y));
            asm("fma.rn.f32x2 %0, %1, %2, %0;" : "+l"(acc10) : "l"(a1d), "l"(bb.x));
            asm("fma.rn.f32x2 %0, %1, %2, %0;" : "+l"(acc11) : "l"(a1d), "l"(bb.y));
        }
        if (t + 1 < T) {
            int nxt = 1 - cur;
            As[nxt][akq + 0][ar] = a4.x; As[nxt][akq + 1][ar] = a4.y;
            As[nxt][akq + 2][ar] = a4.z; As[nxt][akq + 3][ar] = a4.w;
            *(float4*)&Bs[nxt][bkb][bcb]      = b4a;
            *(float4*)&Bs[nxt][bkb + 16][bcb] = b4b;
        }
        __syncthreads();
    }
    float vals[2][4];
    {
        float2 t0 = *(float2*)&acc00, t1 = *(float2*)&acc01;
        float2 t2 = *(float2*)&acc10, t3 = *(float2*)&acc11;
        vals[0][0] = t0.x; vals[0][1] = t0.y; vals[0][2] = t1.x; vals[0][3] = t1.y;
        vals[1][0] = t2.x; vals[1][1] = t2.y; vals[1][2] = t3.x; vals[1][3] = t3.y;
    }
    #pragma unroll
    for (int rr = 0; rr < 2; rr++) {
        int r = row0 + rg * 2 + rr;
        #pragma unroll
        for (int cc = 0; cc < 4; cc++) {
            int c = col0 + cg * 4 + cc;
            float v = vals[rr][cc];
            if (BIAS) v += bias[c];
            if (ACT == 1) v = fmaxf(v, 0.f);
            else if (ACT == 2) {
                float g = 1.f / (1.f + expf(-v));
                v = C[(long)r * ldc + c] * g;
            }
            C[(long)r * ldc + c] = v;
        }
    }
}

// ============================================================
// K1: blocks 0..127 obj-emb GEMM1 split-K; blocks 128.. mask pooling
// ============================================================
__global__ __launch_bounds__(256)
void k1_mask_emb1(const float* __restrict__ roi,
                  const float* __restrict__ logits,
                  const float* __restrict__ bbox,
                  const float* __restrict__ W1,
                  const float* __restrict__ uf,
                  const int* __restrict__ pairs) {
    int bx = blockIdx.x;
    int t = threadIdx.x;
    if (bx < 128) {
        __shared__ float Ae[KCH][33];
        int col0 = (bx & 3) * 64;
        int k0 = (bx >> 2) * KCH;
        for (int idx = t; idx < 32 * KCH; idx += 256) {
            int r = idx / KCH, kk = idx - r * KCH;
            int gk = k0 + kk;
            float v = 0.f;
            if (gk < 4096)      v = roi[r * 4096 + gk];
            else if (gk < 4247) v = logits[r * OC + gk - 4096];
            else if (gk < KIN)  v = bbox[r * 4 + gk - 4247];
            Ae[kk][r] = v;
        }
        __syncthreads();
        int c  = t & 63;
        int rq = t >> 6;
        int col = col0 + c;
        int lenc = KIN - k0; if (lenc > KCH) lenc = KCH;
        float acc[8];
        #pragma unroll
        for (int j = 0; j < 8; j++) acc[j] = 0.f;
        const float* Wp = W1 + (long)k0 * DD + col;
        for (int kk = 0; kk < lenc; kk++) {
            float w = Wp[(long)kk * DD];
            #pragma unroll
            for (int j = 0; j < 8; j++) acc[j] += Ae[kk][rq * 8 + j] * w;
        }
        #pragma unroll
        for (int j = 0; j < 8; j++)
            g_part[((long)(bx >> 2) * 32 + rq * 8 + j) * DD + col] = acc[j];
        return;
    }
    int m = bx - 128;
    int p = m >> 1;
    __shared__ int   code[SP2];
    __shared__ float rect[8];
    if (t == 0) {
        int si = pairs[2 * p], oi = pairs[2 * p + 1];
        float s0 = bbox[4 * si],     s1 = bbox[4 * si + 1];
        float s2 = bbox[4 * si + 2], s3 = bbox[4 * si + 3];
        float o0 = bbox[4 * oi],     o1 = bbox[4 * oi + 1];
        float o2 = bbox[4 * oi + 2], o3 = bbox[4 * oi + 3];
        float ux = fminf(s0, o0), uy = fminf(s1, o1);
        float xs0 = s0 - ux, xs1 = s2 - ux, xo0 = o0 - ux, xo1 = o2 - ux;
        float ys0 = s1 - uy, ys1 = s3 - uy, yo0 = o1 - uy, yo1 = o3 - uy;
        float xr = 14.f / fmaxf(xs1, xo1);
        float yr = 14.f / fmaxf(ys1, yo1);
        rect[0] = rintf(xs0 * xr); rect[1] = rintf(xs1 * xr);
        rect[2] = rintf(ys0 * yr); rect[3] = rintf(ys1 * yr);
        rect[4] = rintf(xo0 * xr); rect[5] = rintf(xo1 * xr);
        rect[6] = rintf(yo0 * yr); rect[7] = rintf(yo1 * yr);
    }
    __syncthreads();
    if (t < SP2) {
        float fi = (float)(t / MM), fj = (float)(t % MM);
        int c = 0;
        if (fi >= rect[0] && fi < rect[1] && fj >= rect[2] && fj < rect[3]) c |= 1;
        if (fi >= rect[4] && fi < rect[5] && fj >= rect[6] && fj < rect[7]) c |= 2;
        code[t] = c;
    }
    __syncthreads();
    int warp = t >> 5, lane = t & 31;
    int d0 = (m & 1) * 128;
    for (int d = d0 + warp; d < d0 + 128; d += 8) {
        const float* base = uf + ((long)p * DD + d) * SP2;
        float ss = 0.f, so = 0.f, sb = 0.f;
        #pragma unroll 7
        for (int e = lane; e < SP2; e += 32) {
            float v = base[e];
            int c = code[e];
            if (c & 1)  ss += v;
            if (c & 2)  so += v;
            if (c == 0) sb += v;
        }
        #pragma unroll
        for (int off = 16; off; off >>= 1) {
            ss += __shfl_xor_sync(0xffffffffu, ss, off);
            so += __shfl_xor_sync(0xffffffffu, so, off);
            sb += __shfl_xor_sync(0xffffffffu, sb, off);
        }
        if (lane == 0) {
            g_sall[p * 768 + d]       = ss / 196.f;
            g_sall[p * 768 + 256 + d] = so / 196.f;
            g_sall[p * 768 + 512 + d] = sb / 196.f;
        }
    }
}

// ============================================================
// K2: blocks 0..185 gateA split-K partials; blocks 186..313 obj_emb2
// ============================================================
__global__ __launch_bounds__(256)
void k2_gateA_emb2(const float* __restrict__ w1a,
                   const float* __restrict__ b_emb1,
                   const float* __restrict__ W2, const float* __restrict__ b2e) {
    int bx = blockIdx.x;
    int t = threadIdx.x;
    if (bx < 186) {
        int z = bx / 62;
        int rem = bx % 62;
        int split = rem / 31;
        int row0 = (rem % 31) * 32;
        gemm_tile_v2<0, 0, 0>(g_sall + z * 256, 0, 0, 768,
                              w1a + (long)z * DD * RED, RED, 0,
                              g_hbp + (long)(split * 3 + z) * PP * RED, RED,
                              row0, 0, 128, split * 128);
        return;
    }
    int j = bx - 186;
    int i = j >> 2, cq = j & 3;
    __shared__ float hid[DD];
    __shared__ float red[4][64];
    {
        float acc = b_emb1[t];
        #pragma unroll 8
        for (int kc = 0; kc < 32; kc++) acc += g_part[(kc * 32 + i) * DD + t];
        hid[t] = fmaxf(acc, 0.f);
    }
    __syncthreads();
    {
        int u = cq * 64 + (t & 63);
        int kq = t >> 6;
        float a0 = 0.f, a1 = 0.f;
        const float* Wp = W2 + u;
        int k0 = kq * 64;
        #pragma unroll 8
        for (int k = k0; k < k0 + 64; k += 2) {
            a0 += hid[k]     * Wp[(k)     * DD];
            a1 += hid[k + 1] * Wp[(k + 1) * DD];
        }
        red[kq][t & 63] = a0 + a1;
    }
    __syncthreads();
    if (t < 64) {
        int u = cq * 64 + t;
        g_feats[i * DD + u] = b2e[u] + red[0][t] + red[1][t] + red[2][t] + red[3][t];
    }
}

// ============================================================
// K3: gateB: g_sall *= sigmoid(relu-combined-H @ w2 + b2). grid 372
// ============================================================
__global__ __launch_bounds__(256)
void k3_gateB(const float* __restrict__ b1a,
              const float* __restrict__ w2a, const float* __restrict__ b2a) {
    int bx = blockIdx.x;
    int z = bx / 124;
    int rem = bx % 124;
    int row0 = (rem >> 2) * 32;
    int col0 = (rem & 3) * 64;
    gemm_tile_v2<1, 2, 1>(g_hbp + (long)z * PP * RED,
                          g_hbp + (long)(3 + z) * PP * RED,
                          b1a + z * RED, RED,
                          w2a + (long)z * RED * DD, DD,
                          b2a + z * DD,
                          g_sall + z * 256, 768,
                          row0, col0, RED, 0);
}

// ============================================================
// K4: rel MLP1 partials. grid (124, 2)
// ============================================================
__global__ __launch_bounds__(256)
void k4_mlp1(const float* __restrict__ W_c1) {
    int bx = blockIdx.x, split = blockIdx.y;
    int row0 = (bx >> 2) * 32, col0 = (bx & 3) * 64;
    gemm_tile_v2<0, 0, 0>(g_sall, 0, 0, 768,
                          W_c1, DD, 0,
                          g_h1p + (long)split * PP * DD, DD,
                          row0, col0, 384, split * 384);
}

// ============================================================
// K5: rel MLP2 partials; A = relu(h1p0+h1p1+b_c1). grid (124, 2)
// ============================================================
__global__ __launch_bounds__(256)
void k5_mlp2(const float* __restrict__ b_c1, const float* __restrict__ W_c2) {
    int bx = blockIdx.x, split = blockIdx.y;
    int row0 = (bx >> 2) * 32, col0 = (bx & 3) * 64;
    gemm_tile_v2<1, 0, 0>(g_h1p, g_h1p + PP * DD, b_c1, DD,
                          W_c2, DD, 0,
                          g_fq + (long)split * PP * DD, DD,
                          row0, col0, 128, split * 128);
}

// ============================================================
// K6: GCN h partials; A = feats (obj rows from g_feats, rel = fq0+fq1+b_c2)
// grid (128, 2)
// ============================================================
__global__ __launch_bounds__(256)
void k6_gcnh(const float* __restrict__ b_c2, const float* __restrict__ W_gcn) {
    int bx = blockIdx.x, split = blockIdx.y;
    int row0 = (bx >> 2) * 32, col0 = (bx & 3) * 64;
    gemm_tile_v2<2, 0, 0>(g_fq, g_fq + PP * DD, b_c2, DD,
                          W_gcn, DD, 0,
                          g_hr + (long)split * (NN + PP) * DD, DD,
                          row0, col0, 128, split * 128);
}

// ============================================================
// K7: fused GCN aggregate + projections. grid 1024. Combines hr halves.
// ============================================================
__global__ __launch_bounds__(256)
void gcn_fused_kernel(const int* __restrict__ pairs,
                      const float* __restrict__ b_gcn,
                      const float* __restrict__ b_c2,
                      const float* __restrict__ W_objp,
                      const float* __restrict__ b_objp,
                      const float* __restrict__ W_relp,
                      const float* __restrict__ b_relp,
                      float* __restrict__ out) {
    int tid = threadIdx.x;
    const float* hr0 = g_hr;
    const float* hr1 = g_hr + (NN + PP) * DD;
    if (blockIdx.x < NN) {
        int i = blockIdx.x;
        __shared__ int sp[PP * 2];
        __shared__ float row[DD];
        for (int k = tid; k < PP * 2; k += 256) sp[k] = pairs[k];
        __syncthreads();
        float acc = hr0[i * DD + tid] + hr1[i * DD + tid];
        int deg = 1;
        for (int p = 0; p < PP; p++) {
            int s = sp[2 * p], o = sp[2 * p + 1];
            if (s == i) {
                acc += hr0[o * DD + tid] + hr1[o * DD + tid];
                acc += hr0[(NN + p) * DD + tid] + hr1[(NN + p) * DD + tid];
                deg += 2;
            } else if (o == i) {
                acc += hr0[(NN + p) * DD + tid] + hr1[(NN + p) * DD + tid];
                deg += 1;
            }
        }
        row[tid] = fmaxf(acc / (float)deg + b_gcn[tid], 0.f) + g_feats[i * DD + tid];
        __syncthreads();
        if (tid < OC) {
            float a0 = b_objp[tid], a1 = 0.f, a2 = 0.f, a3 = 0.f;
            const float* Wp = W_objp + tid;
            #pragma unroll 4
            for (int k = 0; k < DD; k += 4) {
                a0 += row[k]     * Wp[(k)     * OC];
                a1 += row[k + 1] * Wp[(k + 1) * OC];
                a2 += row[k + 2] * Wp[(k + 2) * OC];
                a3 += row[k + 3] * Wp[(k + 3) * OC];
            }
            out[i * OC + tid] = (a0 + a1) + (a2 + a3);
        }
    } else {
        int p = blockIdx.x - NN;
        __shared__ float row[DD];
        __shared__ float ps[4 * RC];
        int s = pairs[2 * p], o = pairs[2 * p + 1];
        float num = hr0[(NN + p) * DD + tid] + hr1[(NN + p) * DD + tid]
                  + hr0[s * DD + tid] + hr1[s * DD + tid];
        float deg = 2.f;
        if (s != o) { num += hr0[o * DD + tid] + hr1[o * DD + tid]; deg = 3.f; }
        float feats_rel = g_fq[p * DD + tid] + g_fq[PP * DD + p * DD + tid] + b_c2[tid];
        row[tid] = fmaxf(num / deg + b_gcn[tid], 0.f) + feats_rel;
        __syncthreads();
        if (tid < 4 * RC) {
            int c = tid % RC, part = tid / RC;
            float a = 0.f;
            int k0 = part * 64;
            #pragma unroll 4
            for (int k = k0; k < k0 + 64; k++) a += row[k] * W_relp[k * RC + c];
            ps[tid] = a;
        }
        __syncthreads();
        if (tid < RC)
            out[NN * OC + p * RC + tid] =
                b_relp[tid] + ps[tid] + ps[RC + tid] + ps[2 * RC + tid] + ps[3 * RC + tid];
    }
}

// ============================================================
// launch
// ============================================================
extern "C" void kernel_launch(void* const* d_in, const int* in_sizes, int n_in,
                              void* d_out, int out_size) {
    const float* roi     = (const float*)d_in[0];
    const float* bbox    = (const float*)d_in[1];
    const float* logits  = (const float*)d_in[2];
    const float* uf      = (const float*)d_in[3];
    const int*   pairs   = (const int*)  d_in[4];
    const float* W_emb1  = (const float*)d_in[5];
    const float* b_emb1  = (const float*)d_in[6];
    const float* W_emb2  = (const float*)d_in[7];
    const float* b_emb2  = (const float*)d_in[8];
    const float* att1w   = (const float*)d_in[9];
    const float* att1b   = (const float*)d_in[10];
    const float* att2w   = (const float*)d_in[11];
    const float* att2b   = (const float*)d_in[12];
    const float* W_c1    = (const float*)d_in[13];
    const float* b_c1    = (const float*)d_in[14];
    const float* W_c2    = (const float*)d_in[15];
    const float* b_c2    = (const float*)d_in[16];
    const float* W_gcn   = (const float*)d_in[17];
    const float* b_gcn   = (const float*)d_in[18];
    const float* W_objp  = (const float*)d_in[19];
    const float* b_objp  = (const float*)d_in[20];
    const float* W_relp  = (const float*)d_in[21];
    const float* b_relp  = (const float*)d_in[22];
    float* out = (float*)d_out;

    // K1: obj-emb GEMM1 + mask pooling (big DRAM pass)
    k1_mask_emb1<<<128 + 2 * PP, 256>>>(roi, logits, bbox, W_emb1, uf, pairs);

    // K2: gateA split-K partials + obj_emb2
    k2_gateA_emb2<<<186 + 128, 256>>>(att1w, b_emb1, W_emb2, b_emb2);

    // K3: gateB (combines gateA partials + relu + b1 in loader), sigmoid*S
    k3_gateB<<<372, 256>>>(att1b, att2w, att2b);

    // K4: rel MLP1 split-K partials
    k4_mlp1<<<dim3(124, 2), 256>>>(W_c1);

    // K5: rel MLP2 split-K partials (A combiner applies relu+b_c1)
    k5_mlp2<<<dim3(124, 2), 256>>>(b_c1, W_c2);

    // K6: GCN h split-K partials (A combiner builds feats)
    k6_gcnh<<<dim3(128, 2), 256>>>(b_c2, W_gcn);

    // K7: GCN aggregate + projections (combines hr halves, writes d_out)
    gcn_fused_kernel<<<NN + PP, 256>>>(pairs, b_gcn, b_c2, W_objp, b_objp,
                                       W_relp, b_relp, out);
}